// round 10
// baseline (speedup 1.0000x reference)
#include <cuda_runtime.h>
#include <math.h>

#define NB 64
#define NS 4096
#define CHUNKS 4
#define CHUNK 1024
#define NTHREADS 128
#define NWARPS 4
#define EPT 8
#define NBLOCKS (NB * CHUNKS)
#define NELEM (NB * NS)
#define EPSF 1e-6f
#define FULLMASK 0xffffffffu
#define SS_STRIDE 85   // 84 floats used; stride 85 -> lane bank stride coprime w/ 32

struct Pose { float qw, qx, qy, qz, tx, ty, tz; };
struct Quat { float w, x, y, z; };

__device__ float  g_agg[NBLOCKS][16];
__device__ float  g_pre[NBLOCKS][16];
__device__ int    g_flag[NBLOCKS];      // gen-coded: 2*gen = agg ready, 2*gen+1 = prefix ready
__device__ double g_accum[6];           // sq_pos, ab_pos, odom_ang, sq_traj, ab_traj, traj_ang
__device__ int    g_gen = 1;
__device__ int    g_done = 0;

__device__ __forceinline__ Pose pidentity() { return Pose{1.f, 0.f, 0.f, 0.f, 0.f, 0.f, 0.f}; }

// C = A then B: q = qa*qb, t = ta + rot(qa, tb)
__device__ __forceinline__ Pose pcompose(const Pose& A, const Pose& B) {
    Pose C;
    C.qw = A.qw*B.qw - A.qx*B.qx - A.qy*B.qy - A.qz*B.qz;
    C.qx = A.qw*B.qx + A.qx*B.qw + A.qy*B.qz - A.qz*B.qy;
    C.qy = A.qw*B.qy - A.qx*B.qz + A.qy*B.qw + A.qz*B.qx;
    C.qz = A.qw*B.qz + A.qx*B.qy - A.qy*B.qx + A.qz*B.qw;
    float t2x = 2.f * (A.qy*B.tz - A.qz*B.ty);
    float t2y = 2.f * (A.qz*B.tx - A.qx*B.tz);
    float t2z = 2.f * (A.qx*B.ty - A.qy*B.tx);
    C.tx = A.tx + B.tx + A.qw*t2x + (A.qy*t2z - A.qz*t2y);
    C.ty = A.ty + B.ty + A.qw*t2y + (A.qz*t2x - A.qx*t2z);
    C.tz = A.tz + B.tz + A.qw*t2z + (A.qx*t2y - A.qy*t2x);
    return C;
}

__device__ __forceinline__ void pnormq(Pose& p) {
    float s = rsqrtf(p.qw*p.qw + p.qx*p.qx + p.qy*p.qy + p.qz*p.qz);
    p.qw *= s; p.qx *= s; p.qy *= s; p.qz *= s;
}

__device__ __forceinline__ Pose pshfl_up(const Pose& p, int off) {
    Pose r;
    r.qw = __shfl_up_sync(FULLMASK, p.qw, off);
    r.qx = __shfl_up_sync(FULLMASK, p.qx, off);
    r.qy = __shfl_up_sync(FULLMASK, p.qy, off);
    r.qz = __shfl_up_sync(FULLMASK, p.qz, off);
    r.tx = __shfl_up_sync(FULLMASK, p.tx, off);
    r.ty = __shfl_up_sync(FULLMASK, p.ty, off);
    r.tz = __shfl_up_sync(FULLMASK, p.tz, off);
    return r;
}

// Quaternion for R = Rz(c) @ Ry(b) @ Rx(a)
__device__ __forceinline__ void euler_to_quat(float a, float b, float c, Pose& P) {
    float sa, ca, sb, cb, sc, cc;
    __sincosf(0.5f * a, &sa, &ca);
    __sincosf(0.5f * b, &sb, &cb);
    __sincosf(0.5f * c, &sc, &cc);
    P.qw = cc*cb*ca + sc*sb*sa;
    P.qx = cc*cb*sa - sc*sb*ca;
    P.qy = cc*sb*ca + sc*cb*sa;
    P.qz = sc*cb*ca - cc*sb*sa;
}

// acos via A&S 4.4.45: |err| <= 2e-8 on [0,1]; input pre-clamped to |x| <= 1-1e-6.
__device__ __forceinline__ float acos_fast(float x) {
    float ax = fabsf(x);
    float p = fmaf(ax, -0.0012624911f, 0.0066700901f);
    p = fmaf(ax, p, -0.0170881256f);
    p = fmaf(ax, p,  0.0308918810f);
    p = fmaf(ax, p, -0.0501743046f);
    p = fmaf(ax, p,  0.0889789874f);
    p = fmaf(ax, p, -0.2145988016f);
    p = fmaf(ax, p,  1.5707963050f);
    float y = 1.0f - ax;                 // >= ~1e-6 after clamp
    float v = (y * rsqrtf(y)) * p;       // sqrt(1-ax) * poly
    return (x >= 0.f) ? v : 3.14159265f - v;
}

__device__ __forceinline__ float clamp_c(float c) {
    return fminf(fmaxf(c, -1.f + EPSF), 1.f - EPSF);
}

__device__ __forceinline__ float qn2p(const Pose& p) {
    return p.qw*p.qw + p.qx*p.qx + p.qy*p.qy + p.qz*p.qz;
}

// conj(g) * e  (Hamilton)
__device__ __forceinline__ Quat qconj_mul(const Pose& g, const Pose& e) {
    Quat r;
    r.w = g.qw*e.qw + g.qx*e.qx + g.qy*e.qy + g.qz*e.qz;
    r.x = g.qw*e.qx - g.qx*e.qw - g.qy*e.qz + g.qz*e.qy;
    r.y = g.qw*e.qy + g.qx*e.qz - g.qy*e.qw - g.qz*e.qx;
    r.z = g.qw*e.qz - g.qx*e.qy + g.qy*e.qx - g.qz*e.qw;
    return r;
}

// dot(r * a.q, b.q)
__device__ __forceinline__ float qmul_dot(const Quat& r, const Pose& a, const Pose& b) {
    float mw = r.w*a.qw - r.x*a.qx - r.y*a.qy - r.z*a.qz;
    float mx = r.w*a.qx + r.x*a.qw + r.y*a.qz - r.z*a.qy;
    float my = r.w*a.qy - r.x*a.qz + r.y*a.qw + r.z*a.qx;
    float mz = r.w*a.qz + r.x*a.qy - r.y*a.qx + r.z*a.qw;
    return mw*b.qw + mx*b.qx + my*b.qy + mz*b.qz;
}

// out = p.t + rot(p.q, x.t)  (translation part of pcompose only)
__device__ __forceinline__ void rot_add(const Pose& p, const Pose& x, float out[3]) {
    float t2x = 2.f * (p.qy*x.tz - p.qz*x.ty);
    float t2y = 2.f * (p.qz*x.tx - p.qx*x.tz);
    float t2z = 2.f * (p.qx*x.ty - p.qy*x.tx);
    out[0] = p.tx + x.tx + p.qw*t2x + (p.qy*t2z - p.qz*t2y);
    out[1] = p.ty + x.ty + p.qw*t2y + (p.qz*t2x - p.qx*t2z);
    out[2] = p.tz + x.tz + p.qw*t2z + (p.qx*t2y - p.qy*t2x);
}

// One trajectory-loss element: translations via rot_add, angle via relative-quat r.
__device__ __forceinline__ void traj_term(
    const Pose& preE, const Pose& preG, const Quat& r, float K,
    const Pose& xE, const Pose& xG, float acc[6]) {
    float tE[3], tG[3];
    rot_add(preE, xE, tE);
    rot_add(preG, xG, tG);
#pragma unroll
    for (int k = 0; k < 3; k++) {
        float d = tE[k] - tG[k];
        acc[3] = fmaf(d, d, acc[3]);
        acc[4] += fabsf(d);
    }
    float dq = qmul_dot(r, xE, xG);
    float nn = K * qn2p(xE) * qn2p(xG);
    float c = clamp_c(fmaf(2.f * dq, __fdividef(dq, nn), -1.f));
    acc[5] += acos_fast(c);
}

__device__ __forceinline__ void pstore_s(float* p, const Pose& x) {
    p[0]=x.qw; p[1]=x.qx; p[2]=x.qy; p[3]=x.qz; p[4]=x.tx; p[5]=x.ty; p[6]=x.tz;
}
__device__ __forceinline__ Pose pload_s(const float* p) {
    Pose x;
    x.qw=p[0]; x.qx=p[1]; x.qy=p[2]; x.qz=p[3]; x.tx=p[4]; x.ty=p[5]; x.tz=p[6];
    return x;
}
__device__ __forceinline__ void pair_store_g(float* p, const Pose& e, const Pose& g) {
    *(float4*)(p)      = make_float4(e.qw, e.qx, e.qy, e.qz);
    *(float4*)(p + 4)  = make_float4(e.tx, e.ty, e.tz, 0.f);
    *(float4*)(p + 8)  = make_float4(g.qw, g.qx, g.qy, g.qz);
    *(float4*)(p + 12) = make_float4(g.tx, g.ty, g.tz, 0.f);
}
__device__ __forceinline__ void pair_load_g(const float* p, Pose& e, Pose& g) {
    float4 a = *(const float4*)(p),     b = *(const float4*)(p + 4);
    float4 c = *(const float4*)(p + 8), d = *(const float4*)(p + 12);
    e.qw=a.x; e.qx=a.y; e.qy=a.z; e.qz=a.w; e.tx=b.x; e.ty=b.y; e.tz=b.z;
    g.qw=c.x; g.qx=c.y; g.qy=c.z; g.qz=c.w; g.tx=d.x; g.ty=d.y; g.tz=d.z;
}

__device__ __forceinline__ void block_reduce6_atomic(float v[6]) {
#pragma unroll
    for (int o = 16; o > 0; o >>= 1)
#pragma unroll
        for (int j = 0; j < 6; j++) v[j] += __shfl_down_sync(FULLMASK, v[j], o);
    __shared__ float w[6][NWARPS];
    int lane = threadIdx.x & 31, wid = threadIdx.x >> 5;
    if (lane == 0)
#pragma unroll
        for (int j = 0; j < 6; j++) w[j][wid] = v[j];
    __syncthreads();
    if (threadIdx.x < 6) {
        double s = 0.0;
#pragma unroll
        for (int i = 0; i < NWARPS; i++) s += (double)w[threadIdx.x][i];
        atomicAdd(&g_accum[threadIdx.x], s);
    }
}

__global__ void __launch_bounds__(NTHREADS) k_main(
    const float* __restrict__ yhat, const float* __restrict__ gpos,
    const float* __restrict__ gori, float* __restrict__ out) {
    // Sub-chain prefixes: E: A0@0 A1@7 A2@14 B0@21 B1@28 B2@35; G: same +42.
    __shared__ float sS[NTHREADS][SS_STRIDE];
    __shared__ float sw[2][NWARPS][8];
    __shared__ float sexc[2][8];
    int tid = threadIdx.x, lane = tid & 31, wid = tid >> 5;
    int bid = blockIdx.x;
    int batch = bid >> 2, chunk = bid & (CHUNKS - 1);
    int s0 = chunk * CHUNK + tid * EPT;
    int idx0 = batch * NS + s0;

    float acc[6] = {0.f, 0.f, 0.f, 0.f, 0.f, 0.f};
    Pose A3E, A3G;   // inclusive of elems 0..3 (regs)
    Pose IE, IG;     // thread-inclusive of all 8 (becomes warp-inclusive after scan)

    // ---- build 8 poses/stream as two 4-element groups (4 chains in flight) ----
#pragma unroll
    for (int g = 0; g < 2; g++) {
        const float4* y4 = (const float4*)(yhat + (size_t)(idx0 + g * 4) * 6);
        float4 y0 = y4[0], y1 = y4[1], y2 = y4[2], y3 = y4[3], y4v = y4[4], y5 = y4[5];
        const float4* o4 = (const float4*)(gori + (size_t)(idx0 + g * 4) * 3);
        float4 q0 = o4[0], q1 = o4[1], q2 = o4[2];
        const float4* p4 = (const float4*)(gpos + (size_t)(idx0 + g * 4) * 3);
        float4 p0 = p4[0], p1 = p4[1], p2 = p4[2];

        float ea[4][3] = {{y0.x,y0.y,y0.z},{y1.z,y1.w,y2.x},{y3.x,y3.y,y3.z},{y4v.z,y4v.w,y5.x}};
        float et[4][3] = {{y0.w,y1.x,y1.y},{y2.y,y2.z,y2.w},{y3.w,y4v.x,y4v.y},{y5.y,y5.z,y5.w}};
        float ga[4][3] = {{q0.x,q0.y,q0.z},{q0.w,q1.x,q1.y},{q1.z,q1.w,q2.x},{q2.y,q2.z,q2.w}};
        float gt[4][3] = {{p0.x,p0.y,p0.z},{p0.w,p1.x,p1.y},{p1.z,p1.w,p2.x},{p2.y,p2.z,p2.w}};

        Pose CE, CG;
#pragma unroll
        for (int i = 0; i < 4; i++) {
            Pose E, G;
            euler_to_quat(ea[i][0], ea[i][1], ea[i][2], E);
            E.tx = et[i][0]; E.ty = et[i][1]; E.tz = et[i][2];
            euler_to_quat(ga[i][0], ga[i][1], ga[i][2], G);
            G.tx = gt[i][0]; G.ty = gt[i][1]; G.tz = gt[i][2];
#pragma unroll
            for (int k = 0; k < 3; k++) {
                float d = (&E.tx)[k] - (&G.tx)[k];
                acc[0] = fmaf(d, d, acc[0]);
                acc[1] += fabsf(d);
            }
            // odom angle: raw quats are unit (|q|=1 +- 4e-6) -> skip normalization
            float dq = E.qw*G.qw + E.qx*G.qx + E.qy*G.qy + E.qz*G.qz;
            acc[2] += acos_fast(clamp_c(fmaf(2.f * dq, dq, -1.f)));
            if (s0 == 0 && g == 0 && i == 0) { E = pidentity(); G = pidentity(); }
            if (i == 0) { CE = E; CG = G; }
            else        { CE = pcompose(CE, E); CG = pcompose(CG, G); }
            if (i < 3) {
                pstore_s(&sS[tid][g * 21 + i * 7], CE);
                pstore_s(&sS[tid][42 + g * 21 + i * 7], CG);
            }
        }
        if (g == 0) { A3E = CE; A3G = CG; }
        else        { IE = pcompose(A3E, CE); IG = pcompose(A3G, CG); }
    }

    Pose TAe = IE, TAg = IG;   // thread aggregates (survive warp scan)

    // ---- warp-level inclusive scan over thread aggregates ----
#pragma unroll
    for (int off = 1; off < 32; off <<= 1) {
        Pose le = pshfl_up(IE, off), lg = pshfl_up(IG, off);
        if (lane >= off) { IE = pcompose(le, IE); IG = pcompose(lg, IG); }
    }
    if (lane == 31) { pstore_s(sw[0][wid], IE); pstore_s(sw[1][wid], IG); }
    __syncthreads();

    // ---- cross-warp scan (warp 0, 4 entries -> 2 steps) ----
    if (wid == 0) {
        Pose te = (lane < NWARPS) ? pload_s(sw[0][lane]) : pidentity();
        Pose tg = (lane < NWARPS) ? pload_s(sw[1][lane]) : pidentity();
#pragma unroll
        for (int off = 1; off < NWARPS; off <<= 1) {
            Pose le = pshfl_up(te, off), lg = pshfl_up(tg, off);
            if (lane >= off && lane < NWARPS) { te = pcompose(le, te); tg = pcompose(lg, tg); }
        }
        if (lane < NWARPS) { pstore_s(sw[0][lane], te); pstore_s(sw[1][lane], tg); }
    }
    __syncthreads();

    // ---- thread 0: publish aggregate, lookback (depth <= 3), publish prefix ----
    if (tid == 0) {
        int gen = *(volatile int*)&g_gen;
        int fagg = 2 * gen, fpre = 2 * gen + 1;
        Pose aE = pload_s(sw[0][NWARPS - 1]);
        Pose aG = pload_s(sw[1][NWARPS - 1]);
        pnormq(aE); pnormq(aG);
        if (chunk < CHUNKS - 1) {
            pair_store_g(g_agg[bid], aE, aG);
            __threadfence();
            atomicExch(&g_flag[bid], fagg);
        }
        Pose excE = pidentity(), excG = pidentity();
        if (chunk > 0) {
            Pose accE = pidentity(), accG = pidentity();
            bool have = false;
            int base = batch * CHUNKS;
            for (int i = bid - 1; i >= base; --i) {
                int f;
                volatile int* vf = g_flag;
                while ((f = vf[i]) < fagg) { __nanosleep(20); }
                __threadfence();
                Pose pE, pG;
                if (f == fpre) {
                    pair_load_g(g_pre[i], pE, pG);
                    excE = pcompose(pE, accE);
                    excG = pcompose(pG, accG);
                    have = true;
                    break;
                } else {
                    pair_load_g(g_agg[i], pE, pG);
                    accE = pcompose(pE, accE);
                    accG = pcompose(pG, accG);
                }
            }
            if (!have) { excE = accE; excG = accG; }
            pnormq(excE); pnormq(excG);
        }
        if (chunk < CHUNKS - 1) {
            Pose pE = pcompose(excE, aE), pG = pcompose(excG, aG);
            pnormq(pE); pnormq(pG);
            pair_store_g(g_pre[bid], pE, pG);
            __threadfence();
            atomicExch(&g_flag[bid], fpre);
        }
        pstore_s(sexc[0], excE);
        pstore_s(sexc[1], excG);
    }
    __syncthreads();

    // ---- apply prefixes, trajectory losses (8 elems) ----
    Pose baseE = pload_s(sexc[0]);
    Pose baseG = pload_s(sexc[1]);
    if (wid > 0) {
        baseE = pcompose(baseE, pload_s(sw[0][wid - 1]));
        baseG = pcompose(baseG, pload_s(sw[1][wid - 1]));
    }
    Pose LEe = pshfl_up(IE, 1), LEg = pshfl_up(IG, 1);
    Pose preE = (lane == 0) ? baseE : pcompose(baseE, LEe);
    Pose preG = (lane == 0) ? baseG : pcompose(baseG, LEg);
    Pose preBE = pcompose(preE, A3E);
    Pose preBG = pcompose(preG, A3G);

    // per-thread relative quats + norm products (amortized over 8 elements)
    Quat r0 = qconj_mul(preG, preE);
    float K0 = qn2p(preE) * qn2p(preG);
    Quat rB = qconj_mul(preBG, preBE);
    float KB = qn2p(preBE) * qn2p(preBG);

    // i = 0..2 (A-group prefixes from smem)
#pragma unroll
    for (int i = 0; i < 3; i++)
        traj_term(preE, preG, r0, K0,
                  pload_s(&sS[tid][i * 7]), pload_s(&sS[tid][42 + i * 7]), acc);
    // i = 3: cumulative = preB; translations are free
    {
#pragma unroll
        for (int k = 0; k < 3; k++) {
            float d = (&preBE.tx)[k] - (&preBG.tx)[k];
            acc[3] = fmaf(d, d, acc[3]);
            acc[4] += fabsf(d);
        }
        float dq = qmul_dot(r0, A3E, A3G);
        float nn = K0 * qn2p(A3E) * qn2p(A3G);
        float c = clamp_c(fmaf(2.f * dq, __fdividef(dq, nn), -1.f));
        acc[5] += acos_fast(c);
    }
    // i = 4..6 (B-group prefixes from smem, base preB)
#pragma unroll
    for (int i = 0; i < 3; i++)
        traj_term(preBE, preBG, rB, KB,
                  pload_s(&sS[tid][21 + i * 7]), pload_s(&sS[tid][63 + i * 7]), acc);
    // i = 7: x = thread aggregate (regs)
    traj_term(preE, preG, r0, K0, TAe, TAg, acc);

    block_reduce6_atomic(acc);
    __syncthreads();

    // ---- last block finalizes ----
    if (tid == 0) {
        __threadfence();
        int old = atomicAdd(&g_done, 1);
        if (old == NBLOCKS - 1) {
            __threadfence();
            const double n3 = (double)NELEM * 3.0, n1 = (double)NELEM;
            double odom = g_accum[2] / n1 + (g_accum[0] / n3 + g_accum[1] / n3);
            double traj = g_accum[5] / n1 + (g_accum[3] / n3 + g_accum[4] / n3);
            out[0] = (float)(0.5 * odom + 0.5 * traj);
#pragma unroll
            for (int j = 0; j < 6; j++) g_accum[j] = 0.0;
            g_done = 0;
            __threadfence();
            g_gen = *(volatile int*)&g_gen + 1;
        }
    }
}

extern "C" void kernel_launch(void* const* d_in, const int* in_sizes, int n_in,
                              void* d_out, int out_size) {
    const float* yhat = (const float*)d_in[0];
    const float* gpos = (const float*)d_in[1];
    const float* gori = (const float*)d_in[2];
    k_main<<<NBLOCKS, NTHREADS>>>(yhat, gpos, gori, (float*)d_out);
}